// round 13
// baseline (speedup 1.0000x reference)
#include <cuda_runtime.h>
#include <cuda_bf16.h>
#include <math.h>
#include <float.h>
#include <stdint.h>

#define BB   8192
#define IND  512
#define DD   256
#define FF   64
#define AA   128
#define NH   8
#define HDIM 16
#define KBUD 16

// ---------------- packed fp32x2 FMA helpers (sm_103a) ----------------
__device__ __forceinline__ void fma2(unsigned long long& d,
                                     unsigned long long a, unsigned long long b) {
    asm("fma.rn.f32x2 %0, %1, %2, %0;" : "+l"(d) : "l"(a), "l"(b));
}
__device__ __forceinline__ unsigned long long bcast2(float x) {
    unsigned long long r;
    asm("mov.b64 %0, {%1, %1};" : "=l"(r) : "f"(x));
    return r;
}
__device__ __forceinline__ float acc_get(const unsigned long long* row, int j) {
    unsigned long long v = row[j >> 1];
    unsigned int u = (j & 1) ? (unsigned int)(v >> 32) : (unsigned int)v;
    return __uint_as_float(u);
}

// 4 m-values x 8 n-values (512-thread tile)
#define GEMM_INNER4_F32X2(AsRow, BsRow, m0, n0, acc2)                             \
    {                                                                             \
        float4 t0 = *reinterpret_cast<const float4*>(&(AsRow)[m0]);               \
        ulonglong2 bu0 = *reinterpret_cast<const ulonglong2*>(&(BsRow)[n0]);      \
        ulonglong2 bu1 = *reinterpret_cast<const ulonglong2*>(&(BsRow)[(n0) + 64]);\
        unsigned long long a2;                                                    \
        a2 = bcast2(t0.x); fma2(acc2[0][0],a2,bu0.x); fma2(acc2[0][1],a2,bu0.y);  \
                           fma2(acc2[0][2],a2,bu1.x); fma2(acc2[0][3],a2,bu1.y);  \
        a2 = bcast2(t0.y); fma2(acc2[1][0],a2,bu0.x); fma2(acc2[1][1],a2,bu0.y);  \
                           fma2(acc2[1][2],a2,bu1.x); fma2(acc2[1][3],a2,bu1.y);  \
        a2 = bcast2(t0.z); fma2(acc2[2][0],a2,bu0.x); fma2(acc2[2][1],a2,bu0.y);  \
                           fma2(acc2[2][2],a2,bu1.x); fma2(acc2[2][3],a2,bu1.y);  \
        a2 = bcast2(t0.w); fma2(acc2[3][0],a2,bu0.x); fma2(acc2[3][1],a2,bu0.y);  \
                           fma2(acc2[3][2],a2,bu1.x); fma2(acc2[3][3],a2,bu1.y);  \
    }

// ---------------- tensor-core / async helpers ----------------
#define LDSM_X4(r0,r1,r2,r3,addr)                                                  \
    asm volatile("ldmatrix.sync.aligned.m8n8.x4.shared.b16 {%0,%1,%2,%3}, [%4];"    \
                 : "=r"(r0),"=r"(r1),"=r"(r2),"=r"(r3) : "r"(addr))

#define MMA16816(d0,d1,d2,d3,a0,a1,a2,a3,b0,b1)                                     \
    asm volatile("mma.sync.aligned.m16n8k16.row.col.f32.bf16.bf16.f32 "             \
                 "{%0,%1,%2,%3}, {%4,%5,%6,%7}, {%8,%9}, {%0,%1,%2,%3};"            \
                 : "+f"(d0),"+f"(d1),"+f"(d2),"+f"(d3)                              \
                 : "r"(a0),"r"(a1),"r"(a2),"r"(a3),"r"(b0),"r"(b1))

#define CP_ASYNC16(dst_u32, src_ptr)                                                \
    asm volatile("cp.async.ca.shared.global [%0], [%1], 16;"                        \
                 :: "r"(dst_u32), "l"(src_ptr))
#define CP_ASYNC_WAIT_ALL()                                                         \
    asm volatile("cp.async.commit_group;\ncp.async.wait_group 0;" ::: "memory")

__device__ __forceinline__ uint32_t smem_u32(const void* p) {
    return (uint32_t)__cvta_generic_to_shared(p);
}

__device__ __forceinline__ uint4 f8_to_h8(float4 x, float4 y) {
    __nv_bfloat162 h0 = __float22bfloat162_rn(make_float2(x.x, x.y));
    __nv_bfloat162 h1 = __float22bfloat162_rn(make_float2(x.z, x.w));
    __nv_bfloat162 h2 = __float22bfloat162_rn(make_float2(y.x, y.y));
    __nv_bfloat162 h3 = __float22bfloat162_rn(make_float2(y.z, y.w));
    uint4 o;
    o.x = *reinterpret_cast<unsigned int*>(&h0);
    o.y = *reinterpret_cast<unsigned int*>(&h1);
    o.z = *reinterpret_cast<unsigned int*>(&h2);
    o.w = *reinterpret_cast<unsigned int*>(&h3);
    return o;
}

__device__ __forceinline__ void bf16x16_to_f32(const __nv_bfloat16* p, float* f) {
    const uint4* q = reinterpret_cast<const uint4*>(p);
    uint4 u0 = q[0], u1 = q[1];
    unsigned int ws[8] = {u0.x, u0.y, u0.z, u0.w, u1.x, u1.y, u1.z, u1.w};
#pragma unroll
    for (int i = 0; i < 8; i++) {
        __nv_bfloat162 h = *reinterpret_cast<__nv_bfloat162*>(&ws[i]);
        float2 t = __bfloat1622float2(h);
        f[2 * i] = t.x; f[2 * i + 1] = t.y;
    }
}

// ---------------- scratch ----------------
__device__ float          g_H[(size_t)BB * 384];
__device__ int            g_cnt[FF];
__device__ int            g_list[(size_t)FF * BB];
__device__ __nv_bfloat16  g_enc[(size_t)BB * KBUD * AA];
__device__ float          g_mctx[(size_t)BB * AA];
__device__ float          g_fiT[AA * FF];
__device__ float          g_sd2T[AA * FF];
__device__ float          g_sd1T[FF * AA];
__device__ float          g_Wc[IND * AA];
__device__ float          g_bc[IND];
__device__ __nv_bfloat16  g_ipwh[384 * AA];
__device__ __nv_bfloat16  g_encwh[(size_t)FF * AA * DD];

// ---------------- K1: fused stage-1 GEMM (fp32 FFMA2, 512T) + prep blocks ----------------
__device__ __forceinline__ const float* k1_wrow(int n, const float* ue_w1,
                                                const float* fi_w1, const float* sd_w1) {
    if (n < AA)     return ue_w1 + (size_t)n * IND;
    if (n < 2 * AA) return fi_w1 + (size_t)(n - AA) * IND;
    return sd_w1 + (size_t)(n - 2 * AA) * (IND + FF);
}

__global__ __launch_bounds__(512) void k_stage1(
    const float* __restrict__ x,
    const float* __restrict__ ue_w1, const float* __restrict__ fi_w1, const float* __restrict__ sd_w1,
    const float* __restrict__ ue_b1, const float* __restrict__ fi_b1, const float* __restrict__ sd_b1,
    const float* __restrict__ fi_w2, const float* __restrict__ sd_w2,
    const float* __restrict__ ipw, const float* __restrict__ enc_w)
{
    const int tid = threadIdx.x;
    if (blockIdx.y >= 64) {
        if (tid >= 256) return;
        const int chunk = (blockIdx.y - 64) * 3 + blockIdx.x;
        if (chunk < 1024) {
            size_t base = (size_t)chunk * 2048 + tid * 8;
            const float4* s = reinterpret_cast<const float4*>(enc_w + base);
            *reinterpret_cast<uint4*>(g_encwh + base) = f8_to_h8(s[0], s[1]);
        } else if (chunk < 1048) {
            size_t base = (size_t)(chunk - 1024) * 2048 + tid * 8;
            const float4* s = reinterpret_cast<const float4*>(ipw + base);
            *reinterpret_cast<uint4*>(g_ipwh + base) = f8_to_h8(s[0], s[1]);
        } else if (chunk < 1144) {
            int idx = (chunk - 1048) * 256 + tid;
            if (idx < 8192) {
                int f = idx >> 7, a = idx & 127;
                g_fiT[a * FF + f] = fi_w2[idx];
            } else if (idx < 16384) {
                int k = idx - 8192;
                int f = k >> 7, a = k & 127;
                g_sd2T[a * FF + f] = sd_w2[k];
            } else {
                int k = idx - 16384;
                int tt = k >> 6, jj = k & 63;
                g_sd1T[jj * AA + tt] = sd_w1[(size_t)tt * (IND + FF) + IND + jj];
            }
        } else if (chunk == 1144) {
            if (tid < FF) g_cnt[tid] = 0;
        }
        return;
    }

    __shared__ float As[16][128];
    __shared__ float Bs[16][128];
    const int row0 = blockIdx.y * 128;
    const int col0 = blockIdx.x * 128;
    const int lm = tid >> 2;           // 0..127
    const int lk = (tid & 3) << 2;     // 0,4,8,12
    const int tx = tid & 15, ty = tid >> 4;   // ty 0..31
    const int m0 = ty * 4, n0 = tx * 4;

    unsigned long long acc2[4][4];
#pragma unroll
    for (int i = 0; i < 4; i++)
#pragma unroll
        for (int j = 0; j < 4; j++) acc2[i][j] = 0ULL;

    const float* a0p = x + (size_t)(row0 + lm) * IND + lk;
    const float* b0p = k1_wrow(col0 + lm, ue_w1, fi_w1, sd_w1) + lk;

    float4 pa0 = *reinterpret_cast<const float4*>(a0p);
    float4 pb0 = *reinterpret_cast<const float4*>(b0p);

    for (int kt = 0; kt < IND; kt += 16) {
        As[lk + 0][lm] = pa0.x; As[lk + 1][lm] = pa0.y; As[lk + 2][lm] = pa0.z; As[lk + 3][lm] = pa0.w;
        Bs[lk + 0][lm] = pb0.x; Bs[lk + 1][lm] = pb0.y; Bs[lk + 2][lm] = pb0.z; Bs[lk + 3][lm] = pb0.w;
        __syncthreads();
        if (kt + 16 < IND) {
            pa0 = *reinterpret_cast<const float4*>(a0p + kt + 16);
            pb0 = *reinterpret_cast<const float4*>(b0p + kt + 16);
        }
#pragma unroll
        for (int k = 0; k < 16; k++) GEMM_INNER4_F32X2(As[k], Bs[k], m0, n0, acc2)
        __syncthreads();
    }

#pragma unroll
    for (int i = 0; i < 4; i++) {
        int m = row0 + m0 + i;
#pragma unroll
        for (int j = 0; j < 8; j++) {
            int n = col0 + n0 + ((j < 4) ? j : 60 + j);
            float v = acc_get(acc2[i], j);
            if (n < AA)          { v += ue_b1[n];          v = fmaxf(v, 0.f); }
            else if (n < 2 * AA) { v += fi_b1[n - AA];     v = fmaxf(v, 0.f); }
            else                 { v += sd_b1[n - 2 * AA]; }
            g_H[(size_t)m * 384 + n] = v;
        }
    }
}

// ---------------- K2: warp-per-row selection (fp32, vectorized loads) ----------------
__global__ __launch_bounds__(256) void k_sel(
    const float* __restrict__ ue_w2, const float* __restrict__ ue_b2,
    const float* __restrict__ fi_b2, const float* __restrict__ sd_b2,
    const float* __restrict__ costs,
    float* __restrict__ out_unc, float* __restrict__ out_fi, float* __restrict__ out_sp,
    float* __restrict__ out_mask, float* __restrict__ out_sc)
{
    __shared__ float shH[8][384];
    __shared__ float shP[8][64];
    __shared__ float shh3[8][128];

    const int w = threadIdx.x >> 5;
    const int l = threadIdx.x & 31;
    const int b = blockIdx.x * 8 + w;

    {
        const float4* src = reinterpret_cast<const float4*>(g_H + (size_t)b * 384);
#pragma unroll
        for (int i = 0; i < 3; i++)
            *reinterpret_cast<float4*>(&shH[w][(l + 32 * i) * 4]) = src[l + 32 * i];
    }
    __syncwarp();

    float s = 0.f;
#pragma unroll
    for (int i = 0; i < 4; i++) s += ue_w2[l + 32 * i] * shH[w][l + 32 * i];
#pragma unroll
    for (int off = 16; off; off >>= 1) s += __shfl_xor_sync(0xffffffffu, s, off);
    const float uval = (float)(1.0 / (1.0 + exp(-(double)(s + ue_b2[0]))));
    if (l == 0) out_unc[b] = uval;

    float lg0 = fi_b2[l], lg1 = fi_b2[l + 32];
#pragma unroll 4
    for (int a = 0; a < AA; a++) {
        const float h = shH[w][AA + a];
        lg0 += g_fiT[a * FF + l]      * h;
        lg1 += g_fiT[a * FF + l + 32] * h;
    }
    float mx = fmaxf(lg0, lg1);
#pragma unroll
    for (int off = 16; off; off >>= 1) mx = fmaxf(mx, __shfl_xor_sync(0xffffffffu, mx, off));
    float e0 = (float)exp((double)(lg0 - mx));
    float e1 = (float)exp((double)(lg1 - mx));
    float sm = e0 + e1;
#pragma unroll
    for (int off = 16; off; off >>= 1) sm += __shfl_xor_sync(0xffffffffu, sm, off);
    const float inv = 1.f / sm;
    const float p0 = e0 * inv, p1 = e1 * inv;
    shP[w][l] = p0; shP[w][l + 32] = p1;
    out_fi[(size_t)b * FF + l] = p0;
    out_fi[(size_t)b * FF + l + 32] = p1;
    __syncwarp();

#pragma unroll
    for (int i = 0; i < 4; i++) {
        const int t = l + 32 * i;
        float v = shH[w][2 * AA + t];
#pragma unroll 4
        for (int j = 0; j < FF; j++) v += g_sd1T[j * AA + t] * shP[w][j];
        shh3[w][t] = fmaxf(v, 0.f);
    }
    __syncwarp();

    float a0 = sd_b2[l], a1 = sd_b2[l + 32];
#pragma unroll 4
    for (int c = 0; c < AA; c++) {
        const float h = shh3[w][c];
        a0 += g_sd2T[c * FF + l]      * h;
        a1 += g_sd2T[c * FF + l + 32] * h;
    }
    const float q0 = (float)(1.0 / (1.0 + exp(-(double)a0)));
    const float q1 = (float)(1.0 / (1.0 + exp(-(double)a1)));
    out_sp[(size_t)b * FF + l] = q0;
    out_sp[(size_t)b * FF + l + 32] = q1;
    const float c0 = costs[l], c1 = costs[l + 32];
    const float adj0 = q0 / (1.f + c0) * uval;
    const float adj1 = q1 / (1.f + c1) * uval;

    bool pk0 = false, pk1 = false;
    int mypick = 0;
#pragma unroll
    for (int it = 0; it < KBUD; it++) {
        float v0 = pk0 ? -FLT_MAX : adj0;
        float v1 = pk1 ? -FLT_MAX : adj1;
        float bv; int bi;
        if (v1 > v0) { bv = v1; bi = l + 32; } else { bv = v0; bi = l; }
#pragma unroll
        for (int off = 16; off; off >>= 1) {
            float ov = __shfl_xor_sync(0xffffffffu, bv, off);
            int   oi = __shfl_xor_sync(0xffffffffu, bi, off);
            if (ov > bv || (ov == bv && oi < bi)) { bv = ov; bi = oi; }
        }
        if (bi == l)      pk0 = true;
        if (bi == l + 32) pk1 = true;
        if (l == it)      mypick = bi;
    }

    out_mask[(size_t)b * FF + l]      = pk0 ? 1.f : 0.f;
    out_mask[(size_t)b * FF + l + 32] = pk1 ? 1.f : 0.f;
    float cs = (pk0 ? c0 : 0.f) + (pk1 ? c1 : 0.f);
#pragma unroll
    for (int off = 16; off; off >>= 1) cs += __shfl_xor_sync(0xffffffffu, cs, off);
    if (l == 0) out_sc[b] = cs;

    if (l < KBUD) {
        int pos = atomicAdd(&g_cnt[mypick], 1);
        g_list[(size_t)mypick * BB + pos] = (b << 4) | l;
    }
}

// ---------------- K3: grouped gather-encoder GEMM (bf16 TC, precvt weights) + combine ----------------
#define ENC_STRIDE 264
#define ENC_SMEM_BYTES 136192

__global__ __launch_bounds__(256, 1) void k_enc(
    const float* __restrict__ af, const float* __restrict__ enc_b,
    const float* __restrict__ opw, const float* __restrict__ outpw,
    const float* __restrict__ outpb, const float* __restrict__ opb)
{
    const int tid = threadIdx.x;
    if (blockIdx.y == FF) {
        const int i = blockIdx.x * 8 + (tid >> 5);
        const int c0 = (tid & 31) * 4;
        float acc0 = 0.f, acc1 = 0.f, acc2 = 0.f, acc3 = 0.f;
#pragma unroll 4
        for (int a = 0; a < AA; a++) {
            float w = opw[(size_t)i * AA + a];
            const float4 v = *reinterpret_cast<const float4*>(outpw + (size_t)a * AA + c0);
            acc0 += w * v.x; acc1 += w * v.y; acc2 += w * v.z; acc3 += w * v.w;
        }
        float* o = g_Wc + (size_t)i * AA + c0;
        o[0] = acc0; o[1] = acc1; o[2] = acc2; o[3] = acc3;
        if (tid < 8) {
            int r = blockIdx.x * 8 + tid;
            float s = opb[r];
#pragma unroll 4
            for (int a = 0; a < AA; a++) s += outpb[a] * opw[(size_t)r * AA + a];
            g_bc[r] = s;
        }
        return;
    }

    const int f = blockIdx.y;
    const int cnt = g_cnt[f];
    const int row0 = blockIdx.x * 128;
    if (row0 >= cnt) return;

    extern __shared__ char smem_raw[];
    __nv_bfloat16* Ash = reinterpret_cast<__nv_bfloat16*>(smem_raw);
    __nv_bfloat16* Bsh = reinterpret_cast<__nv_bfloat16*>(smem_raw + 67584);
    float*         biasS = reinterpret_cast<float*>(smem_raw + 135168);
    int*           ents  = reinterpret_cast<int*>(smem_raw + 135680);

    const int lane = tid & 31;
    const int w = tid >> 5;
    const int wm = w & 1, wn = w >> 1;

    if (tid < 128) {
        ents[tid] = (row0 + tid < cnt) ? g_list[(size_t)f * BB + row0 + tid] : -1;
        biasS[tid] = enc_b[f * AA + tid];
    }
    __syncthreads();

    {
        const int r = tid >> 1, half = tid & 1;
        const int e = ents[r];
        __nv_bfloat16* adst = Ash + r * ENC_STRIDE + half * 128;
        if (e >= 0) {
            const float4* src = reinterpret_cast<const float4*>(
                af + ((size_t)f * BB + (e >> 4)) * DD + half * 128);
#pragma unroll
            for (int i = 0; i < 16; i++)
                reinterpret_cast<uint4*>(adst)[i] = f8_to_h8(src[2 * i], src[2 * i + 1]);
        } else {
            uint4 z = make_uint4(0, 0, 0, 0);
#pragma unroll
            for (int i = 0; i < 16; i++) reinterpret_cast<uint4*>(adst)[i] = z;
        }
        const __nv_bfloat16* bsrc = g_encwh + ((size_t)f * AA + r) * DD + half * 128;
        uint32_t bdst = smem_u32(Bsh + r * ENC_STRIDE + half * 128);
#pragma unroll
        for (int i = 0; i < 16; i++) CP_ASYNC16(bdst + 16 * i, bsrc + 8 * i);
        CP_ASYNC_WAIT_ALL();
    }
    __syncthreads();

    float dacc[4][4][4];
#pragma unroll
    for (int mt = 0; mt < 4; mt++)
#pragma unroll
        for (int nt = 0; nt < 4; nt++)
#pragma unroll
            for (int r = 0; r < 4; r++) dacc[mt][nt][r] = 0.f;

    const int a_row = (lane & 15);
    const int a_koff = (lane >> 4) << 3;
    const int b_noff = (lane & 7) + ((lane >> 4) << 3);
    const int b_koff = ((lane >> 3) & 1) << 3;

    for (int ks = 0; ks < DD / 16; ks++) {
        const int k0 = ks * 16;
        uint32_t a[4][4];
#pragma unroll
        for (int mt = 0; mt < 4; mt++) {
            uint32_t ad = smem_u32(Ash + (wm * 64 + mt * 16 + a_row) * ENC_STRIDE + k0 + a_koff);
            LDSM_X4(a[mt][0], a[mt][1], a[mt][2], a[mt][3], ad);
        }
        uint32_t bfr[4][2];
#pragma unroll
        for (int ntp = 0; ntp < 2; ntp++) {
            uint32_t bd = smem_u32(Bsh + (wn * 32 + ntp * 16 + b_noff) * ENC_STRIDE + k0 + b_koff);
            uint32_t r0, r1, r2, r3;
            LDSM_X4(r0, r1, r2, r3, bd);
            bfr[2 * ntp][0] = r0;     bfr[2 * ntp][1] = r1;
            bfr[2 * ntp + 1][0] = r2; bfr[2 * ntp + 1][1] = r3;
        }
#pragma unroll
        for (int mt = 0; mt < 4; mt++)
#pragma unroll
            for (int nt = 0; nt < 4; nt++)
                MMA16816(dacc[mt][nt][0], dacc[mt][nt][1], dacc[mt][nt][2], dacc[mt][nt][3],
                         a[mt][0], a[mt][1], a[mt][2], a[mt][3], bfr[nt][0], bfr[nt][1]);
    }

    const int t4 = lane >> 2, tc = (lane & 3) * 2;
#pragma unroll
    for (int mt = 0; mt < 4; mt++) {
#pragma unroll
        for (int nt = 0; nt < 4; nt++) {
            const int c_ = wn * 32 + nt * 8 + tc;
            const float b0 = biasS[c_], b1 = biasS[c_ + 1];
            const int r1_ = wm * 64 + mt * 16 + t4;
            const int e1 = ents[r1_];
            if (e1 >= 0) {
                __nv_bfloat162 hv = __float22bfloat162_rn(
                    make_float2(dacc[mt][nt][0] + b0, dacc[mt][nt][1] + b1));
                *reinterpret_cast<__nv_bfloat162*>(
                    g_enc + ((size_t)(e1 >> 4) * KBUD + (e1 & 15)) * AA + c_) = hv;
            }
            const int r2_ = r1_ + 8;
            const int e2 = ents[r2_];
            if (e2 >= 0) {
                __nv_bfloat162 hv = __float22bfloat162_rn(
                    make_float2(dacc[mt][nt][2] + b0, dacc[mt][nt][3] + b1));
                *reinterpret_cast<__nv_bfloat162*>(
                    g_enc + ((size_t)(e2 >> 4) * KBUD + (e2 & 15)) * AA + c_) = hv;
            }
        }
    }
}

// ---------------- generic tiled GEMM (fp32 FFMA2, 512T) ----------------
__global__ __launch_bounds__(512) void k_gemm(
    const float* __restrict__ Am, const float* __restrict__ W,
    const float* __restrict__ bias, const float* __restrict__ addsrc,
    float* __restrict__ C, int M, int N, int K)
{
    __shared__ float As[16][128];
    __shared__ float Bs[16][128];
    const int tid  = threadIdx.x;
    const int row0 = blockIdx.y * 128;
    const int col0 = blockIdx.x * 128;
    const int lm = tid >> 2;
    const int lk = (tid & 3) << 2;
    const int tx = tid & 15, ty = tid >> 4;
    const int m0 = ty * 4, n0 = tx * 4;

    unsigned long long acc2[4][4];
#pragma unroll
    for (int i = 0; i < 4; i++)
#pragma unroll
        for (int j = 0; j < 4; j++) acc2[i][j] = 0ULL;

    const float* a0p = Am + (size_t)(row0 + lm) * K + lk;
    const float* b0p = W + (size_t)(col0 + lm) * K + lk;

    float4 pa0 = *reinterpret_cast<const float4*>(a0p);
    float4 pb0 = *reinterpret_cast<const float4*>(b0p);

    for (int kt = 0; kt < K; kt += 16) {
        As[lk + 0][lm] = pa0.x; As[lk + 1][lm] = pa0.y; As[lk + 2][lm] = pa0.z; As[lk + 3][lm] = pa0.w;
        Bs[lk + 0][lm] = pb0.x; Bs[lk + 1][lm] = pb0.y; Bs[lk + 2][lm] = pb0.z; Bs[lk + 3][lm] = pb0.w;
        __syncthreads();
        if (kt + 16 < K) {
            pa0 = *reinterpret_cast<const float4*>(a0p + kt + 16);
            pb0 = *reinterpret_cast<const float4*>(b0p + kt + 16);
        }
#pragma unroll
        for (int k = 0; k < 16; k++) GEMM_INNER4_F32X2(As[k], Bs[k], m0, n0, acc2)
        __syncthreads();
    }

#pragma unroll
    for (int i = 0; i < 4; i++) {
        int m = row0 + m0 + i;
#pragma unroll
        for (int j = 0; j < 8; j++) {
            int n = col0 + n0 + ((j < 4) ? j : 60 + j);
            float v = acc_get(acc2[i], j);
            if (bias)   v += bias[n];
            if (addsrc) v += addsrc[(size_t)m * N + n];
            C[(size_t)m * N + n] = v;
        }
    }
}

// ---------------- K4+K5 fused (128 rows/block, 512 threads / 16 warps) ----------------
#define QKV_H_STRIDE 408
#define FUS_AB_STRIDE 136
#define FUSED_SMEM_BYTES 176384

__global__ __launch_bounds__(512, 1) void k_fused(const float* __restrict__ ipb)
{
    extern __shared__ char smem_raw[];
    __nv_bfloat16* Ash  = reinterpret_cast<__nv_bfloat16*>(smem_raw);
    __nv_bfloat16* Bsh  = reinterpret_cast<__nv_bfloat16*>(smem_raw + 34816);
    __nv_bfloat16* qkvs = reinterpret_cast<__nv_bfloat16*>(smem_raw + 69632);
    float*         pb   = reinterpret_cast<float*>(smem_raw + 174080);
    __nv_bfloat16* pbh  = reinterpret_cast<__nv_bfloat16*>(smem_raw + 175616);

    const int tid = threadIdx.x;
    const int lane = tid & 31;
    const int w = tid >> 5;
    const int wm = w & 3, wn = w >> 2;
    const int row0 = blockIdx.x * 128;

    if (tid < 192) {
        float2 v = *reinterpret_cast<const float2*>(ipb + 2 * tid);
        pb[2 * tid] = v.x; pb[2 * tid + 1] = v.y;
        *reinterpret_cast<__nv_bfloat162*>(pbh + 2 * tid) =
            __float22bfloat162_rn(make_float2(v.x, v.y));
    }

    {
        const int r = tid >> 2, seg = tid & 3;
        const __nv_bfloat16* src = g_enc + (size_t)(row0 + r) * AA + seg * 32;
        uint32_t dst = smem_u32(Ash + r * FUS_AB_STRIDE + seg * 32);
#pragma unroll
        for (int i = 0; i < 4; i++) CP_ASYNC16(dst + 16 * i, src + 8 * i);
    }
    {
        const int r = tid >> 2, seg = tid & 3;
        const __nv_bfloat16* src = g_ipwh + (size_t)r * AA + seg * 32;
        uint32_t dst = smem_u32(Bsh + r * FUS_AB_STRIDE + seg * 32);
#pragma unroll
        for (int i = 0; i < 4; i++) CP_ASYNC16(dst + 16 * i, src + 8 * i);
    }
    CP_ASYNC_WAIT_ALL();
    __syncthreads();

    const int a_row = (lane & 15);
    const int a_koff = (lane >> 4) << 3;
    const int b_noff = (lane & 7) + ((lane >> 4) << 3);
    const int b_koff = ((lane >> 3) & 1) << 3;
    const int t4 = lane >> 2, tc = (lane & 3) * 2;

    for (int chunk = 0; chunk < 3; chunk++) {
        float dacc[2][4][4];
#pragma unroll
        for (int mt = 0; mt < 2; mt++)
#pragma unroll
            for (int nt = 0; nt < 4; nt++)
#pragma unroll
                for (int r = 0; r < 4; r++) dacc[mt][nt][r] = 0.f;

        for (int ks = 0; ks < AA / 16; ks++) {
            const int k0 = ks * 16;
            uint32_t a[2][4];
#pragma unroll
            for (int mt = 0; mt < 2; mt++) {
                uint32_t ad = smem_u32(Ash + (wm * 32 + mt * 16 + a_row) * FUS_AB_STRIDE + k0 + a_koff);
                LDSM_X4(a[mt][0], a[mt][1], a[mt][2], a[mt][3], ad);
            }
            uint32_t bfr[4][2];
#pragma unroll
            for (int ntp = 0; ntp < 2; ntp++) {
                uint32_t bd = smem_u32(Bsh + (wn * 32 + ntp * 16 + b_noff) * FUS_AB_STRIDE + k0 + b_koff);
                uint32_t r0, r1, r2, r3;
                LDSM_X4(r0, r1, r2, r3, bd);
                bfr[2 * ntp][0] = r0;     bfr[2 * ntp][1] = r1;
                bfr[2 * ntp + 1][0] = r2; bfr[2 * ntp + 1][1] = r3;
            }
#pragma unroll
            for (int mt = 0; mt < 2; mt++)
#pragma unroll
                for (int nt = 0; nt < 4; nt++)
                    MMA16816(dacc[mt][nt][0], dacc[mt][nt][1], dacc[mt][nt][2], dacc[mt][nt][3],
                             a[mt][0], a[mt][1], a[mt][2], a[mt][3], bfr[nt][0], bfr[nt][1]);
        }

#pragma unroll
        for (int mt = 0; mt < 2; mt++) {
#pragma unroll
            for (int nt = 0; nt < 4; nt++) {
                const int c_ = wn * 32 + nt * 8 + tc;
                const int gc = chunk * 128 + c_;
                const float b0 = pb[gc], b1 = pb[gc + 1];
                const int r1_ = wm * 32 + mt * 16 + t4;
                *reinterpret_cast<__nv_bfloat162*>(qkvs + r1_ * QKV_H_STRIDE + gc) =
                    __float22bfloat162_rn(make_float2(dacc[mt][nt][0] + b0, dacc[mt][nt][1] + b1));
                *reinterpret_cast<__nv_bfloat162*>(qkvs + (r1_ + 8) * QKV_H_STRIDE + gc) =
                    __float22bfloat162_rn(make_float2(dacc[mt][nt][2] + b0, dacc[mt][nt][3] + b1));
            }
        }
        __syncthreads();

        if (chunk < 2) {
            const int r = tid >> 2, seg = tid & 3;
            const __nv_bfloat16* src = g_ipwh + (size_t)((chunk + 1) * 128 + r) * AA + seg * 32;
            uint32_t dst = smem_u32(Bsh + r * FUS_AB_STRIDE + seg * 32);
#pragma unroll
            for (int i = 0; i < 4; i++) CP_ASYNC16(dst + 16 * i, src + 8 * i);
            CP_ASYNC_WAIT_ALL();
            __syncthreads();
        }
    }

    // ---- attention: 16 warps; warp w -> head w&7, batch-group w>>3 ----
    const int h = w & 7, bgrp = w >> 3, l = lane;
    const int hb = h * HDIM;
    const int batch0 = blockIdx.x * 8;

    float* warp_kv = reinterpret_cast<float*>(smem_raw) + w * 640;
    float* scores  = reinterpret_cast<float*>(smem_raw + 40960) + w * 306;

    for (int bl2 = 0; bl2 < 4; bl2++) {
        const int bl = bgrp * 4 + bl2;
        {
            const int r = lane & 15;
            const bool isK = lane < 16;
            const __nv_bfloat16* src = qkvs + (bl * 16 + r) * QKV_H_STRIDE
                                       + (isK ? AA : 2 * AA) + hb;
            float tmp[16];
            bf16x16_to_f32(src, tmp);
            float* dst = warp_kv + (isK ? 0 : 320) + r * 20;
#pragma unroll
            for (int c = 0; c < 16; c++) dst[c] = tmp[c];
        }
        __syncwarp();

        float ctx[16];
#pragma unroll
        for (int c = 0; c < 16; c++) ctx[c] = 0.f;

        if (l < 17) {
            float q[16];
            if (l < 16) bf16x16_to_f32(qkvs + (bl * 16 + l) * QKV_H_STRIDE + hb, q);
            else {
#pragma unroll
                for (int c = 0; c < 16; c++) q[c] = pb[hb + c];
            }

            float mxv = -FLT_MAX;
#pragma unroll
            for (int tk = 0; tk < 17; tk++) {
                const float4* kk = reinterpret_cast<const float4*>(
                    (tk < 16) ? (warp_kv + tk * 20) : (pb + AA + hb));
                float4 k0 = kk[0], k1 = kk[1], k2 = kk[2], k3 = kk[3];
                float d = q[0]*k0.x + q[1]*k0.y + q[2]*k0.z + q[3]*k0.w
                        + q[4]*k1.x + q[5]*k1.y + q[6]*k1.z + q[7]*k1.w
                        + q[8]*k2.x + q[9]*k2.y + q[10]*k2.z + q[11]*k2.w
                        + q[12]*k3.x + q[13]*k3.y + q[14]*k3.z + q[15]*k3.w;
                d *= 0.25f;
                scores[l * 18 + tk] = d;
                mxv = fmaxf(mxv, d);
            }

            float den = 0.f;
#pragma unroll
            for (int tk = 0; tk < 17; tk++) {
                float wgt = expf(scores[l * 18 + tk] - mxv);
                if (tk == 16) wgt *= 48.f;
                den += wgt;
                const float4* vv = reinterpret_cast<const float4*>(
                    (tk < 16) ? (warp_kv + 320 + tk * 20) : (pb + 2 * AA + hb));
                float4 v0 = vv[0], v1 = vv[1], v2 = vv[2], v3 = vv[3];
                ctx[0]  += wgt*v0.x; ctx[1]  += wgt*v0.y; ctx[2]  += wgt*v0.z; ctx[3]  += wgt*v0.w;
                ctx[4]  += wgt*v1.x; ctx[5]  += wgt*v1.y; ctx[6]  += wgt*v1.z; ctx[7]  += wgt*v1.w;
                ctx[8]  += wgt*v2.x; ctx[9]  += wgt*v2.y; ctx[10] += wgt*v2.z; ctx[11] += wgt*v2.w;
                ctx[12] += wgt*v3.x; ctx[13] += wgt*v3.y; ctx[14] += wgt*v3.z; ctx[15] += wgt*v3.w;
            }
            const float qw = ((l < 16) ? 1.f : 48.f) / den;
#pragma unroll
            for (int c = 0; c < 16; c++) ctx[c] *= qw;
        }

#pragma unroll
        for (int c = 0; c < 16; c++) {
            float v = ctx[c];
#pragma unroll
            for (int off = 16; off; off >>= 1) v += __shfl_xor_sync(0xffffffffu, v, off);
            ctx[c] = v;
        }
        if (l == 0) {
            float* dst = g_mctx + (size_t)(batch0 + bl) * AA + hb;
            const float sc = 1.f / 64.f;
#pragma unroll
            for (int c = 0; c < 16; c++) dst[c] = ctx[c] * sc;
        }
        __syncwarp();
    }
}

// ---------------- launch ----------------
extern "C" void kernel_launch(void* const* d_in, const int* in_sizes, int n_in,
                              void* d_out, int out_size)
{
    const float* x     = (const float*)d_in[0];
    const float* af    = (const float*)d_in[1];
    const float* costs = (const float*)d_in[2];
    const float* ue_w1 = (const float*)d_in[3];
    const float* ue_b1 = (const float*)d_in[4];
    const float* ue_w2 = (const float*)d_in[5];
    const float* ue_b2 = (const float*)d_in[6];
    const float* fi_w1 = (const float*)d_in[7];
    const float* fi_b1 = (const float*)d_in[8];
    const float* fi_w2 = (const float*)d_in[9];
    const float* fi_b2 = (const float*)d_in[10];
    const float* sd_w1 = (const float*)d_in[11];
    const float* sd_b1 = (const float*)d_in[12];
    const float* sd_w2 = (const float*)d_in[13];
    const float* sd_b2 = (const float*)d_in[14];
    const float* enc_w = (const float*)d_in[15];
    const float* enc_b = (const float*)d_in[16];
    const float* ipw   = (const float*)d_in[17];
    const float* ipb   = (const float*)d_in[18];
    const float* outpw = (const float*)d_in[19];
    const float* outpb = (const float*)d_in[20];
    const float* opw   = (const float*)d_in[21];
    const float* opb   = (const float*)d_in[22];

    float* out    = (float*)d_out;
    float* o_enh  = out;
    float* o_unc  = o_enh + (size_t)BB * IND;
    float* o_fi   = o_unc + BB;
    float* o_sp   = o_fi + (size_t)BB * FF;
    float* o_mask = o_sp + (size_t)BB * FF;
    float* o_sc   = o_mask + (size_t)BB * FF;

    cudaFuncSetAttribute(k_fused, cudaFuncAttributeMaxDynamicSharedMemorySize,
                         FUSED_SMEM_BYTES);
    cudaFuncSetAttribute(k_enc, cudaFuncAttributeMaxDynamicSharedMemorySize,
                         ENC_SMEM_BYTES);

    k_stage1<<<dim3(3, 446), 512>>>(x, ue_w1, fi_w1, sd_w1,
                                    ue_b1, fi_b1, sd_b1, fi_w2, sd_w2,
                                    ipw, enc_w);                                // 1
    k_sel<<<BB / 8, 256>>>(ue_w2, ue_b2, fi_b2, sd_b2, costs,
                           o_unc, o_fi, o_sp, o_mask, o_sc);                    // 2
    k_enc<<<dim3(BB / 128, FF + 1), 256, ENC_SMEM_BYTES>>>(af, enc_b,
                                           opw, outpw, outpb, opb);             // 3
    k_fused<<<BB / 8, 512, FUSED_SMEM_BYTES>>>(ipb);                            // 4 <- profiled
    k_gemm<<<dim3(4, BB / 128), 512>>>(g_mctx, g_Wc, g_bc, x, o_enh,
                                       BB, IND, AA);                            // 5
}

// round 14
// speedup vs baseline: 1.0573x; 1.0573x over previous
#include <cuda_runtime.h>
#include <cuda_bf16.h>
#include <math.h>
#include <float.h>
#include <stdint.h>

#define BB   8192
#define IND  512
#define DD   256
#define FF   64
#define AA   128
#define NH   8
#define HDIM 16
#define KBUD 16

// ---------------- packed fp32x2 FMA helpers (sm_103a) ----------------
__device__ __forceinline__ void fma2(unsigned long long& d,
                                     unsigned long long a, unsigned long long b) {
    asm("fma.rn.f32x2 %0, %1, %2, %0;" : "+l"(d) : "l"(a), "l"(b));
}
__device__ __forceinline__ unsigned long long bcast2(float x) {
    unsigned long long r;
    asm("mov.b64 %0, {%1, %1};" : "=l"(r) : "f"(x));
    return r;
}
__device__ __forceinline__ float acc_get(const unsigned long long* row, int j) {
    unsigned long long v = row[j >> 1];
    unsigned int u = (j & 1) ? (unsigned int)(v >> 32) : (unsigned int)v;
    return __uint_as_float(u);
}

// 8 m-values x 8 n-values (256-thread tile, measured-best)
#define GEMM_INNER_F32X2(AsRow, BsRow, m0, n0, acc2)                              \
    {                                                                             \
        float4 t0 = *reinterpret_cast<const float4*>(&(AsRow)[m0]);               \
        float4 t1 = *reinterpret_cast<const float4*>(&(AsRow)[(m0) + 64]);        \
        ulonglong2 bu0 = *reinterpret_cast<const ulonglong2*>(&(BsRow)[n0]);      \
        ulonglong2 bu1 = *reinterpret_cast<const ulonglong2*>(&(BsRow)[(n0) + 64]);\
        unsigned long long a2;                                                    \
        a2 = bcast2(t0.x); fma2(acc2[0][0],a2,bu0.x); fma2(acc2[0][1],a2,bu0.y);  \
                           fma2(acc2[0][2],a2,bu1.x); fma2(acc2[0][3],a2,bu1.y);  \
        a2 = bcast2(t0.y); fma2(acc2[1][0],a2,bu0.x); fma2(acc2[1][1],a2,bu0.y);  \
                           fma2(acc2[1][2],a2,bu1.x); fma2(acc2[1][3],a2,bu1.y);  \
        a2 = bcast2(t0.z); fma2(acc2[2][0],a2,bu0.x); fma2(acc2[2][1],a2,bu0.y);  \
                           fma2(acc2[2][2],a2,bu1.x); fma2(acc2[2][3],a2,bu1.y);  \
        a2 = bcast2(t0.w); fma2(acc2[3][0],a2,bu0.x); fma2(acc2[3][1],a2,bu0.y);  \
                           fma2(acc2[3][2],a2,bu1.x); fma2(acc2[3][3],a2,bu1.y);  \
        a2 = bcast2(t1.x); fma2(acc2[4][0],a2,bu0.x); fma2(acc2[4][1],a2,bu0.y);  \
                           fma2(acc2[4][2],a2,bu1.x); fma2(acc2[4][3],a2,bu1.y);  \
        a2 = bcast2(t1.y); fma2(acc2[5][0],a2,bu0.x); fma2(acc2[5][1],a2,bu0.y);  \
                           fma2(acc2[5][2],a2,bu1.x); fma2(acc2[5][3],a2,bu1.y);  \
        a2 = bcast2(t1.z); fma2(acc2[6][0],a2,bu0.x); fma2(acc2[6][1],a2,bu0.y);  \
                           fma2(acc2[6][2],a2,bu1.x); fma2(acc2[6][3],a2,bu1.y);  \
        a2 = bcast2(t1.w); fma2(acc2[7][0],a2,bu0.x); fma2(acc2[7][1],a2,bu0.y);  \
                           fma2(acc2[7][2],a2,bu1.x); fma2(acc2[7][3],a2,bu1.y);  \
    }

// ---------------- tensor-core / async helpers ----------------
#define LDSM_X4(r0,r1,r2,r3,addr)                                                  \
    asm volatile("ldmatrix.sync.aligned.m8n8.x4.shared.b16 {%0,%1,%2,%3}, [%4];"    \
                 : "=r"(r0),"=r"(r1),"=r"(r2),"=r"(r3) : "r"(addr))

#define MMA16816(d0,d1,d2,d3,a0,a1,a2,a3,b0,b1)                                     \
    asm volatile("mma.sync.aligned.m16n8k16.row.col.f32.bf16.bf16.f32 "             \
                 "{%0,%1,%2,%3}, {%4,%5,%6,%7}, {%8,%9}, {%0,%1,%2,%3};"            \
                 : "+f"(d0),"+f"(d1),"+f"(d2),"+f"(d3)                              \
                 : "r"(a0),"r"(a1),"r"(a2),"r"(a3),"r"(b0),"r"(b1))

#define CP_ASYNC16(dst_u32, src_ptr)                                                \
    asm volatile("cp.async.ca.shared.global [%0], [%1], 16;"                        \
                 :: "r"(dst_u32), "l"(src_ptr))
#define CP_ASYNC_COMMIT()                                                           \
    asm volatile("cp.async.commit_group;" ::: "memory")
#define CP_ASYNC_WAIT_ALL()                                                         \
    asm volatile("cp.async.commit_group;\ncp.async.wait_group 0;" ::: "memory")
#define CP_ASYNC_WAIT0()                                                            \
    asm volatile("cp.async.wait_group 0;" ::: "memory")

__device__ __forceinline__ uint32_t smem_u32(const void* p) {
    return (uint32_t)__cvta_generic_to_shared(p);
}

__device__ __forceinline__ uint4 f8_to_h8(float4 x, float4 y) {
    __nv_bfloat162 h0 = __float22bfloat162_rn(make_float2(x.x, x.y));
    __nv_bfloat162 h1 = __float22bfloat162_rn(make_float2(x.z, x.w));
    __nv_bfloat162 h2 = __float22bfloat162_rn(make_float2(y.x, y.y));
    __nv_bfloat162 h3 = __float22bfloat162_rn(make_float2(y.z, y.w));
    uint4 o;
    o.x = *reinterpret_cast<unsigned int*>(&h0);
    o.y = *reinterpret_cast<unsigned int*>(&h1);
    o.z = *reinterpret_cast<unsigned int*>(&h2);
    o.w = *reinterpret_cast<unsigned int*>(&h3);
    return o;
}

__device__ __forceinline__ void bf16x16_to_f32(const __nv_bfloat16* p, float* f) {
    const uint4* q = reinterpret_cast<const uint4*>(p);
    uint4 u0 = q[0], u1 = q[1];
    unsigned int ws[8] = {u0.x, u0.y, u0.z, u0.w, u1.x, u1.y, u1.z, u1.w};
#pragma unroll
    for (int i = 0; i < 8; i++) {
        __nv_bfloat162 h = *reinterpret_cast<__nv_bfloat162*>(&ws[i]);
        float2 t = __bfloat1622float2(h);
        f[2 * i] = t.x; f[2 * i + 1] = t.y;
    }
}

// ---------------- scratch ----------------
__device__ float          g_H[(size_t)BB * 384];
__device__ int            g_cnt[FF];
__device__ int            g_list[(size_t)FF * BB];
__device__ __nv_bfloat16  g_enc[(size_t)BB * KBUD * AA];
__device__ float          g_mctx[(size_t)BB * AA];
__device__ float          g_fiT[AA * FF];
__device__ float          g_sd2T[AA * FF];
__device__ float          g_sd1T[FF * AA];
__device__ float          g_Wc[IND * AA];
__device__ float          g_bc[IND];
__device__ __nv_bfloat16  g_ipwh[384 * AA];
__device__ __nv_bfloat16  g_encwh[(size_t)FF * AA * DD];

// ---------------- K1: fused stage-1 GEMM (fp32 FFMA2, 256T) + prep blocks ----------------
__device__ __forceinline__ const float* k1_wrow(int n, const float* ue_w1,
                                                const float* fi_w1, const float* sd_w1) {
    if (n < AA)     return ue_w1 + (size_t)n * IND;
    if (n < 2 * AA) return fi_w1 + (size_t)(n - AA) * IND;
    return sd_w1 + (size_t)(n - 2 * AA) * (IND + FF);
}

__global__ __launch_bounds__(256) void k_stage1(
    const float* __restrict__ x,
    const float* __restrict__ ue_w1, const float* __restrict__ fi_w1, const float* __restrict__ sd_w1,
    const float* __restrict__ ue_b1, const float* __restrict__ fi_b1, const float* __restrict__ sd_b1,
    const float* __restrict__ fi_w2, const float* __restrict__ sd_w2,
    const float* __restrict__ ipw, const float* __restrict__ enc_w)
{
    const int tid = threadIdx.x;
    if (blockIdx.y >= 64) {
        const int chunk = (blockIdx.y - 64) * 3 + blockIdx.x;
        if (chunk < 1024) {
            size_t base = (size_t)chunk * 2048 + tid * 8;
            const float4* s = reinterpret_cast<const float4*>(enc_w + base);
            *reinterpret_cast<uint4*>(g_encwh + base) = f8_to_h8(s[0], s[1]);
        } else if (chunk < 1048) {
            size_t base = (size_t)(chunk - 1024) * 2048 + tid * 8;
            const float4* s = reinterpret_cast<const float4*>(ipw + base);
            *reinterpret_cast<uint4*>(g_ipwh + base) = f8_to_h8(s[0], s[1]);
        } else if (chunk < 1144) {
            int idx = (chunk - 1048) * 256 + tid;
            if (idx < 8192) {
                int f = idx >> 7, a = idx & 127;
                g_fiT[a * FF + f] = fi_w2[idx];
            } else if (idx < 16384) {
                int k = idx - 8192;
                int f = k >> 7, a = k & 127;
                g_sd2T[a * FF + f] = sd_w2[k];
            } else {
                int k = idx - 16384;
                int tt = k >> 6, jj = k & 63;
                g_sd1T[jj * AA + tt] = sd_w1[(size_t)tt * (IND + FF) + IND + jj];
            }
        } else if (chunk == 1144) {
            if (tid < FF) g_cnt[tid] = 0;
        }
        return;
    }

    __shared__ float As[16][128];
    __shared__ float Bs[16][128];
    const int row0 = blockIdx.y * 128;
    const int col0 = blockIdx.x * 128;
    const int lm = tid >> 2;
    const int lk = (tid & 3) << 2;
    const int tx = tid & 15, ty = tid >> 4;
    const int m0 = ty * 4, n0 = tx * 4;

    unsigned long long acc2[8][4];
#pragma unroll
    for (int i = 0; i < 8; i++)
#pragma unroll
        for (int j = 0; j < 4; j++) acc2[i][j] = 0ULL;

    const float* a0p = x + (size_t)(row0 + lm) * IND + lk;
    const float* a1p = x + (size_t)(row0 + lm + 64) * IND + lk;
    const float* b0p = k1_wrow(col0 + lm, ue_w1, fi_w1, sd_w1) + lk;
    const float* b1p = k1_wrow(col0 + lm + 64, ue_w1, fi_w1, sd_w1) + lk;

    float4 pa0 = *reinterpret_cast<const float4*>(a0p);
    float4 pa1 = *reinterpret_cast<const float4*>(a1p);
    float4 pb0 = *reinterpret_cast<const float4*>(b0p);
    float4 pb1 = *reinterpret_cast<const float4*>(b1p);

    for (int kt = 0; kt < IND; kt += 16) {
        As[lk + 0][lm] = pa0.x; As[lk + 1][lm] = pa0.y; As[lk + 2][lm] = pa0.z; As[lk + 3][lm] = pa0.w;
        As[lk + 0][lm + 64] = pa1.x; As[lk + 1][lm + 64] = pa1.y; As[lk + 2][lm + 64] = pa1.z; As[lk + 3][lm + 64] = pa1.w;
        Bs[lk + 0][lm] = pb0.x; Bs[lk + 1][lm] = pb0.y; Bs[lk + 2][lm] = pb0.z; Bs[lk + 3][lm] = pb0.w;
        Bs[lk + 0][lm + 64] = pb1.x; Bs[lk + 1][lm + 64] = pb1.y; Bs[lk + 2][lm + 64] = pb1.z; Bs[lk + 3][lm + 64] = pb1.w;
        __syncthreads();
        if (kt + 16 < IND) {
            pa0 = *reinterpret_cast<const float4*>(a0p + kt + 16);
            pa1 = *reinterpret_cast<const float4*>(a1p + kt + 16);
            pb0 = *reinterpret_cast<const float4*>(b0p + kt + 16);
            pb1 = *reinterpret_cast<const float4*>(b1p + kt + 16);
        }
#pragma unroll
        for (int k = 0; k < 16; k++) GEMM_INNER_F32X2(As[k], Bs[k], m0, n0, acc2)
        __syncthreads();
    }

#pragma unroll
    for (int i = 0; i < 8; i++) {
        int m = row0 + m0 + ((i < 4) ? i : 60 + i);
#pragma unroll
        for (int j = 0; j < 8; j++) {
            int n = col0 + n0 + ((j < 4) ? j : 60 + j);
            float v = acc_get(acc2[i], j);
            if (n < AA)          { v += ue_b1[n];          v = fmaxf(v, 0.f); }
            else if (n < 2 * AA) { v += fi_b1[n - AA];     v = fmaxf(v, 0.f); }
            else                 { v += sd_b1[n - 2 * AA]; }
            g_H[(size_t)m * 384 + n] = v;
        }
    }
}

// ---------------- K2: warp-per-row selection (fp32, vectorized loads) ----------------
__global__ __launch_bounds__(256) void k_sel(
    const float* __restrict__ ue_w2, const float* __restrict__ ue_b2,
    const float* __restrict__ fi_b2, const float* __restrict__ sd_b2,
    const float* __restrict__ costs,
    float* __restrict__ out_unc, float* __restrict__ out_fi, float* __restrict__ out_sp,
    float* __restrict__ out_mask, float* __restrict__ out_sc)
{
    __shared__ float shH[8][384];
    __shared__ float shP[8][64];
    __shared__ float shh3[8][128];

    const int w = threadIdx.x >> 5;
    const int l = threadIdx.x & 31;
    const int b = blockIdx.x * 8 + w;

    {
        const float4* src = reinterpret_cast<const float4*>(g_H + (size_t)b * 384);
#pragma unroll
        for (int i = 0; i < 3; i++)
            *reinterpret_cast<float4*>(&shH[w][(l + 32 * i) * 4]) = src[l + 32 * i];
    }
    __syncwarp();

    float s = 0.f;
#pragma unroll
    for (int i = 0; i < 4; i++) s += ue_w2[l + 32 * i] * shH[w][l + 32 * i];
#pragma unroll
    for (int off = 16; off; off >>= 1) s += __shfl_xor_sync(0xffffffffu, s, off);
    const float uval = (float)(1.0 / (1.0 + exp(-(double)(s + ue_b2[0]))));
    if (l == 0) out_unc[b] = uval;

    float lg0 = fi_b2[l], lg1 = fi_b2[l + 32];
#pragma unroll 4
    for (int a = 0; a < AA; a++) {
        const float h = shH[w][AA + a];
        lg0 += g_fiT[a * FF + l]      * h;
        lg1 += g_fiT[a * FF + l + 32] * h;
    }
    float mx = fmaxf(lg0, lg1);
#pragma unroll
    for (int off = 16; off; off >>= 1) mx = fmaxf(mx, __shfl_xor_sync(0xffffffffu, mx, off));
    float e0 = (float)exp((double)(lg0 - mx));
    float e1 = (float)exp((double)(lg1 - mx));
    float sm = e0 + e1;
#pragma unroll
    for (int off = 16; off; off >>= 1) sm += __shfl_xor_sync(0xffffffffu, sm, off);
    const float inv = 1.f / sm;
    const float p0 = e0 * inv, p1 = e1 * inv;
    shP[w][l] = p0; shP[w][l + 32] = p1;
    out_fi[(size_t)b * FF + l] = p0;
    out_fi[(size_t)b * FF + l + 32] = p1;
    __syncwarp();

#pragma unroll
    for (int i = 0; i < 4; i++) {
        const int t = l + 32 * i;
        float v = shH[w][2 * AA + t];
#pragma unroll 4
        for (int j = 0; j < FF; j++) v += g_sd1T[j * AA + t] * shP[w][j];
        shh3[w][t] = fmaxf(v, 0.f);
    }
    __syncwarp();

    float a0 = sd_b2[l], a1 = sd_b2[l + 32];
#pragma unroll 4
    for (int c = 0; c < AA; c++) {
        const float h = shh3[w][c];
        a0 += g_sd2T[c * FF + l]      * h;
        a1 += g_sd2T[c * FF + l + 32] * h;
    }
    const float q0 = (float)(1.0 / (1.0 + exp(-(double)a0)));
    const float q1 = (float)(1.0 / (1.0 + exp(-(double)a1)));
    out_sp[(size_t)b * FF + l] = q0;
    out_sp[(size_t)b * FF + l + 32] = q1;
    const float c0 = costs[l], c1 = costs[l + 32];
    const float adj0 = q0 / (1.f + c0) * uval;
    const float adj1 = q1 / (1.f + c1) * uval;

    bool pk0 = false, pk1 = false;
    int mypick = 0;
#pragma unroll
    for (int it = 0; it < KBUD; it++) {
        float v0 = pk0 ? -FLT_MAX : adj0;
        float v1 = pk1 ? -FLT_MAX : adj1;
        float bv; int bi;
        if (v1 > v0) { bv = v1; bi = l + 32; } else { bv = v0; bi = l; }
#pragma unroll
        for (int off = 16; off; off >>= 1) {
            float ov = __shfl_xor_sync(0xffffffffu, bv, off);
            int   oi = __shfl_xor_sync(0xffffffffu, bi, off);
            if (ov > bv || (ov == bv && oi < bi)) { bv = ov; bi = oi; }
        }
        if (bi == l)      pk0 = true;
        if (bi == l + 32) pk1 = true;
        if (l == it)      mypick = bi;
    }

    out_mask[(size_t)b * FF + l]      = pk0 ? 1.f : 0.f;
    out_mask[(size_t)b * FF + l + 32] = pk1 ? 1.f : 0.f;
    float cs = (pk0 ? c0 : 0.f) + (pk1 ? c1 : 0.f);
#pragma unroll
    for (int off = 16; off; off >>= 1) cs += __shfl_xor_sync(0xffffffffu, cs, off);
    if (l == 0) out_sc[b] = cs;

    if (l < KBUD) {
        int pos = atomicAdd(&g_cnt[mypick], 1);
        g_list[(size_t)mypick * BB + pos] = (b << 4) | l;
    }
}

// ---------------- K3: grouped gather-encoder GEMM (bf16 TC, precvt weights) + combine ----------------
#define ENC_STRIDE 264
#define ENC_SMEM_BYTES 136192

__global__ __launch_bounds__(256, 1) void k_enc(
    const float* __restrict__ af, const float* __restrict__ enc_b,
    const float* __restrict__ opw, const float* __restrict__ outpw,
    const float* __restrict__ outpb, const float* __restrict__ opb)
{
    const int tid = threadIdx.x;
    if (blockIdx.y == FF) {
        const int i = blockIdx.x * 8 + (tid >> 5);
        const int c0 = (tid & 31) * 4;
        float acc0 = 0.f, acc1 = 0.f, acc2 = 0.f, acc3 = 0.f;
#pragma unroll 4
        for (int a = 0; a < AA; a++) {
            float w = opw[(size_t)i * AA + a];
            const float4 v = *reinterpret_cast<const float4*>(outpw + (size_t)a * AA + c0);
            acc0 += w * v.x; acc1 += w * v.y; acc2 += w * v.z; acc3 += w * v.w;
        }
        float* o = g_Wc + (size_t)i * AA + c0;
        o[0] = acc0; o[1] = acc1; o[2] = acc2; o[3] = acc3;
        if (tid < 8) {
            int r = blockIdx.x * 8 + tid;
            float s = opb[r];
#pragma unroll 4
            for (int a = 0; a < AA; a++) s += outpb[a] * opw[(size_t)r * AA + a];
            g_bc[r] = s;
        }
        return;
    }

    const int f = blockIdx.y;
    const int cnt = g_cnt[f];
    const int row0 = blockIdx.x * 128;
    if (row0 >= cnt) return;

    extern __shared__ char smem_raw[];
    __nv_bfloat16* Ash = reinterpret_cast<__nv_bfloat16*>(smem_raw);
    __nv_bfloat16* Bsh = reinterpret_cast<__nv_bfloat16*>(smem_raw + 67584);
    float*         biasS = reinterpret_cast<float*>(smem_raw + 135168);
    int*           ents  = reinterpret_cast<int*>(smem_raw + 135680);

    const int lane = tid & 31;
    const int w = tid >> 5;
    const int wm = w & 1, wn = w >> 1;

    if (tid < 128) {
        ents[tid] = (row0 + tid < cnt) ? g_list[(size_t)f * BB + row0 + tid] : -1;
        biasS[tid] = enc_b[f * AA + tid];
    }
    __syncthreads();

    {
        const int r = tid >> 1, half = tid & 1;
        const int e = ents[r];
        __nv_bfloat16* adst = Ash + r * ENC_STRIDE + half * 128;
        if (e >= 0) {
            const float4* src = reinterpret_cast<const float4*>(
                af + ((size_t)f * BB + (e >> 4)) * DD + half * 128);
#pragma unroll
            for (int i = 0; i < 16; i++)
                reinterpret_cast<uint4*>(adst)[i] = f8_to_h8(src[2 * i], src[2 * i + 1]);
        } else {
            uint4 z = make_uint4(0, 0, 0, 0);
#pragma unroll
            for (int i = 0; i < 16; i++) reinterpret_cast<uint4*>(adst)[i] = z;
        }
        const __nv_bfloat16* bsrc = g_encwh + ((size_t)f * AA + r) * DD + half * 128;
        uint32_t bdst = smem_u32(Bsh + r * ENC_STRIDE + half * 128);
#pragma unroll
        for (int i = 0; i < 16; i++) CP_ASYNC16(bdst + 16 * i, bsrc + 8 * i);
        CP_ASYNC_WAIT_ALL();
    }
    __syncthreads();

    float dacc[4][4][4];
#pragma unroll
    for (int mt = 0; mt < 4; mt++)
#pragma unroll
        for (int nt = 0; nt < 4; nt++)
#pragma unroll
            for (int r = 0; r < 4; r++) dacc[mt][nt][r] = 0.f;

    const int a_row = (lane & 15);
    const int a_koff = (lane >> 4) << 3;
    const int b_noff = (lane & 7) + ((lane >> 4) << 3);
    const int b_koff = ((lane >> 3) & 1) << 3;

    for (int ks = 0; ks < DD / 16; ks++) {
        const int k0 = ks * 16;
        uint32_t a[4][4];
#pragma unroll
        for (int mt = 0; mt < 4; mt++) {
            uint32_t ad = smem_u32(Ash + (wm * 64 + mt * 16 + a_row) * ENC_STRIDE + k0 + a_koff);
            LDSM_X4(a[mt][0], a[mt][1], a[mt][2], a[mt][3], ad);
        }
        uint32_t bfr[4][2];
#pragma unroll
        for (int ntp = 0; ntp < 2; ntp++) {
            uint32_t bd = smem_u32(Bsh + (wn * 32 + ntp * 16 + b_noff) * ENC_STRIDE + k0 + b_koff);
            uint32_t r0, r1, r2, r3;
            LDSM_X4(r0, r1, r2, r3, bd);
            bfr[2 * ntp][0] = r0;     bfr[2 * ntp][1] = r1;
            bfr[2 * ntp + 1][0] = r2; bfr[2 * ntp + 1][1] = r3;
        }
#pragma unroll
        for (int mt = 0; mt < 4; mt++)
#pragma unroll
            for (int nt = 0; nt < 4; nt++)
                MMA16816(dacc[mt][nt][0], dacc[mt][nt][1], dacc[mt][nt][2], dacc[mt][nt][3],
                         a[mt][0], a[mt][1], a[mt][2], a[mt][3], bfr[nt][0], bfr[nt][1]);
    }

    const int t4 = lane >> 2, tc = (lane & 3) * 2;
#pragma unroll
    for (int mt = 0; mt < 4; mt++) {
#pragma unroll
        for (int nt = 0; nt < 4; nt++) {
            const int c_ = wn * 32 + nt * 8 + tc;
            const float b0 = biasS[c_], b1 = biasS[c_ + 1];
            const int r1_ = wm * 64 + mt * 16 + t4;
            const int e1 = ents[r1_];
            if (e1 >= 0) {
                __nv_bfloat162 hv = __float22bfloat162_rn(
                    make_float2(dacc[mt][nt][0] + b0, dacc[mt][nt][1] + b1));
                *reinterpret_cast<__nv_bfloat162*>(
                    g_enc + ((size_t)(e1 >> 4) * KBUD + (e1 & 15)) * AA + c_) = hv;
            }
            const int r2_ = r1_ + 8;
            const int e2 = ents[r2_];
            if (e2 >= 0) {
                __nv_bfloat162 hv = __float22bfloat162_rn(
                    make_float2(dacc[mt][nt][2] + b0, dacc[mt][nt][3] + b1));
                *reinterpret_cast<__nv_bfloat162*>(
                    g_enc + ((size_t)(e2 >> 4) * KBUD + (e2 & 15)) * AA + c_) = hv;
            }
        }
    }
}

// ---------------- generic tiled GEMM (fp32 FFMA2, 256T) ----------------
__global__ __launch_bounds__(256) void k_gemm(
    const float* __restrict__ Am, const float* __restrict__ W,
    const float* __restrict__ bias, const float* __restrict__ addsrc,
    float* __restrict__ C, int M, int N, int K)
{
    __shared__ float As[16][128];
    __shared__ float Bs[16][128];
    const int tid  = threadIdx.x;
    const int row0 = blockIdx.y * 128;
    const int col0 = blockIdx.x * 128;
    const int lm = tid >> 2;
    const int lk = (tid & 3) << 2;
    const int tx = tid & 15, ty = tid >> 4;
    const int m0 = ty * 4, n0 = tx * 4;

    unsigned long long acc2[8][4];
#pragma unroll
    for (int i = 0; i < 8; i++)
#pragma unroll
        for (int j = 0; j < 4; j++) acc2[i][j] = 0ULL;

    const float* a0p = Am + (size_t)(row0 + lm) * K + lk;
    const float* a1p = Am + (size_t)(row0 + lm + 64) * K + lk;
    const float* b0p = W + (size_t)(col0 + lm) * K + lk;
    const float* b1p = W + (size_t)(col0 + lm + 64) * K + lk;

    float4 pa0 = *reinterpret_cast<const float4*>(a0p);
    float4 pa1 = *reinterpret_cast<const float4*>(a1p);
    float4 pb0 = *reinterpret_cast<const float4*>(b0p);
    float4 pb1 = *reinterpret_cast<const float4*>(b1p);

    for (int kt = 0; kt < K; kt += 16) {
        As[lk + 0][lm] = pa0.x; As[lk + 1][lm] = pa0.y; As[lk + 2][lm] = pa0.z; As[lk + 3][lm] = pa0.w;
        As[lk + 0][lm + 64] = pa1.x; As[lk + 1][lm + 64] = pa1.y; As[lk + 2][lm + 64] = pa1.z; As[lk + 3][lm + 64] = pa1.w;
        Bs[lk + 0][lm] = pb0.x; Bs[lk + 1][lm] = pb0.y; Bs[lk + 2][lm] = pb0.z; Bs[lk + 3][lm] = pb0.w;
        Bs[lk + 0][lm + 64] = pb1.x; Bs[lk + 1][lm + 64] = pb1.y; Bs[lk + 2][lm + 64] = pb1.z; Bs[lk + 3][lm + 64] = pb1.w;
        __syncthreads();
        if (kt + 16 < K) {
            pa0 = *reinterpret_cast<const float4*>(a0p + kt + 16);
            pa1 = *reinterpret_cast<const float4*>(a1p + kt + 16);
            pb0 = *reinterpret_cast<const float4*>(b0p + kt + 16);
            pb1 = *reinterpret_cast<const float4*>(b1p + kt + 16);
        }
#pragma unroll
        for (int k = 0; k < 16; k++) GEMM_INNER_F32X2(As[k], Bs[k], m0, n0, acc2)
        __syncthreads();
    }

#pragma unroll
    for (int i = 0; i < 8; i++) {
        int m = row0 + m0 + ((i < 4) ? i : 60 + i);
#pragma unroll
        for (int j = 0; j < 8; j++) {
            int n = col0 + n0 + ((j < 4) ? j : 60 + j);
            float v = acc_get(acc2[i], j);
            if (bias)   v += bias[n];
            if (addsrc) v += addsrc[(size_t)m * N + n];
            C[(size_t)m * N + n] = v;
        }
    }
}

// ---------------- K4+K5 fused (128 rows/block, 512T/16 warps, double-buffered B) ----------------
// dyn smem (bytes): Ash bf16[128][136] @0 (34816) | Bsh0 @34816 (34816) | Bsh1 @69632 (34816) |
// qkvs bf16[128][408] @104448 (104448) | pb f32[384] @208896 (1536) | pbh bf16[384] @210432 (768)
// Attention scratch overlaps Ash/Bsh0: warp_kv f32 @0 (16x640=40960B) | scores @40960 (16x306)
#define QKV_H_STRIDE 408
#define FUS_AB_STRIDE 136
#define FUSED_SMEM_BYTES 211200

__global__ __launch_bounds__(512, 1) void k_fused(const float* __restrict__ ipb)
{
    extern __shared__ char smem_raw[];
    __nv_bfloat16* Ash  = reinterpret_cast<__nv_bfloat16*>(smem_raw);
    __nv_bfloat16* Bsh0 = reinterpret_cast<__nv_bfloat16*>(smem_raw + 34816);
    __nv_bfloat16* Bsh1 = reinterpret_cast<__nv_bfloat16*>(smem_raw + 69632);
    __nv_bfloat16* qkvs = reinterpret_cast<__nv_bfloat16*>(smem_raw + 104448);
    float*         pb   = reinterpret_cast<float*>(smem_raw + 208896);
    __nv_bfloat16* pbh  = reinterpret_cast<__nv_bfloat16*>(smem_raw + 210432);

    const int tid = threadIdx.x;
    const int lane = tid & 31;
    const int w = tid >> 5;
    const int wm = w & 3, wn = w >> 2;
    const int row0 = blockIdx.x * 128;

    if (tid < 192) {
        float2 v = *reinterpret_cast<const float2*>(ipb + 2 * tid);
        pb[2 * tid] = v.x; pb[2 * tid + 1] = v.y;
        *reinterpret_cast<__nv_bfloat162*>(pbh + 2 * tid) =
            __float22bfloat162_rn(make_float2(v.x, v.y));
    }

    // stage A + B chunk0 (cp.async)
    {
        const int r = tid >> 2, seg = tid & 3;
        const __nv_bfloat16* asrc = g_enc + (size_t)(row0 + r) * AA + seg * 32;
        uint32_t adst = smem_u32(Ash + r * FUS_AB_STRIDE + seg * 32);
#pragma unroll
        for (int i = 0; i < 4; i++) CP_ASYNC16(adst + 16 * i, asrc + 8 * i);
        const __nv_bfloat16* bsrc = g_ipwh + (size_t)r * AA + seg * 32;
        uint32_t bdst = smem_u32(Bsh0 + r * FUS_AB_STRIDE + seg * 32);
#pragma unroll
        for (int i = 0; i < 4; i++) CP_ASYNC16(bdst + 16 * i, bsrc + 8 * i);
    }
    CP_ASYNC_WAIT_ALL();
    __syncthreads();

    const int a_row = (lane & 15);
    const int a_koff = (lane >> 4) << 3;
    const int b_noff = (lane & 7) + ((lane >> 4) << 3);
    const int b_koff = ((lane >> 3) & 1) << 3;
    const int t4 = lane >> 2, tc = (lane & 3) * 2;

    for (int chunk = 0; chunk < 3; chunk++) {
        __nv_bfloat16* Bcur = (chunk & 1) ? Bsh1 : Bsh0;
        // prefetch next B chunk into the other buffer (hidden under MMA)
        if (chunk < 2) {
            __nv_bfloat16* Bnext = (chunk & 1) ? Bsh0 : Bsh1;
            const int r = tid >> 2, seg = tid & 3;
            const __nv_bfloat16* src = g_ipwh + (size_t)((chunk + 1) * 128 + r) * AA + seg * 32;
            uint32_t dst = smem_u32(Bnext + r * FUS_AB_STRIDE + seg * 32);
#pragma unroll
            for (int i = 0; i < 4; i++) CP_ASYNC16(dst + 16 * i, src + 8 * i);
            CP_ASYNC_COMMIT();
        }

        float dacc[2][4][4];
#pragma unroll
        for (int mt = 0; mt < 2; mt++)
#pragma unroll
            for (int nt = 0; nt < 4; nt++)
#pragma unroll
                for (int r = 0; r < 4; r++) dacc[mt][nt][r] = 0.f;

        for (int ks = 0; ks < AA / 16; ks++) {
            const int k0 = ks * 16;
            uint32_t a[2][4];
#pragma unroll
            for (int mt = 0; mt < 2; mt++) {
                uint32_t ad = smem_u32(Ash + (wm * 32 + mt * 16 + a_row) * FUS_AB_STRIDE + k0 + a_koff);
                LDSM_X4(a[mt][0], a[mt][1], a[mt][2], a[mt][3], ad);
            }
            uint32_t bfr[4][2];
#pragma unroll
            for (int ntp = 0; ntp < 2; ntp++) {
                uint32_t bd = smem_u32(Bcur + (wn * 32 + ntp * 16 + b_noff) * FUS_AB_STRIDE + k0 + b_koff);
                uint32_t r0, r1, r2, r3;
                LDSM_X4(r0, r1, r2, r3, bd);
                bfr[2 * ntp][0] = r0;     bfr[2 * ntp][1] = r1;
                bfr[2 * ntp + 1][0] = r2; bfr[2 * ntp + 1][1] = r3;
            }
#pragma unroll
            for (int mt = 0; mt < 2; mt++)
#pragma unroll
                for (int nt = 0; nt < 4; nt++)
                    MMA16816(dacc[mt][nt][0], dacc[mt][nt][1], dacc[mt][nt][2], dacc[mt][nt][3],
                             a[mt][0], a[mt][1], a[mt][2], a[mt][3], bfr[nt][0], bfr[nt][1]);
        }

        // epilogue: +bias, bf16 into qkvs
#pragma unroll
        for (int mt = 0; mt < 2; mt++) {
#pragma unroll
            for (int nt = 0; nt < 4; nt++) {
                const int c_ = wn * 32 + nt * 8 + tc;
                const int gc = chunk * 128 + c_;
                const float b0 = pb[gc], b1 = pb[gc + 1];
                const int r1_ = wm * 32 + mt * 16 + t4;
                *reinterpret_cast<__nv_bfloat162*>(qkvs + r1_ * QKV_H_STRIDE + gc) =
                    __float22bfloat162_rn(make_float2(dacc[mt][nt][0] + b0, dacc[mt][nt][1] + b1));
                *reinterpret_cast<__nv_bfloat162*>(qkvs + (r1_ + 8) * QKV_H_STRIDE + gc) =
                    __float22bfloat162_rn(make_float2(dacc[mt][nt][2] + b0, dacc[mt][nt][3] + b1));
            }
        }

        if (chunk < 2) {
            CP_ASYNC_WAIT0();
            __syncthreads();
        }
    }
    __syncthreads();

    // ---- attention: 16 warps; warp w -> head w&7, batch-group w>>3 ----
    const int h = w & 7, bgrp = w >> 3, l = lane;
    const int hb = h * HDIM;
    const int batch0 = blockIdx.x * 8;

    float* warp_kv = reinterpret_cast<float*>(smem_raw) + w * 640;
    float* scores  = reinterpret_cast<float*>(smem_raw + 40960) + w * 306;

    for (int bl2 = 0; bl2 < 4; bl2++) {
        const int bl = bgrp * 4 + bl2;
        {
            const int r = lane & 15;
            const bool isK = lane < 16;
            const __nv_bfloat16* src = qkvs + (bl * 16 + r) * QKV_H_STRIDE
                                       + (isK ? AA : 2 * AA) + hb;
            float tmp[16];
            bf16x16_to_f32(src, tmp);
            float* dst = warp_kv + (isK ? 0 : 320) + r * 20;
#pragma unroll
            for (int c = 0; c < 16; c++) dst[c] = tmp[c];
        }
        __syncwarp();

        float ctx[16];
#pragma unroll
        for (int c = 0; c < 16; c++) ctx[c] = 0.f;

        if (l < 17) {
            float q[16];
            if (l < 16) bf16x16_to_f32(qkvs + (bl * 16 + l) * QKV_H_STRIDE + hb, q);
            else {
#pragma unroll
                for (int c = 0; c < 16; c++) q[c] = pb[hb + c];
            }

            float mxv = -FLT_MAX;
#pragma unroll
            for (int tk = 0; tk < 17; tk++) {
                const float4* kk = reinterpret_cast<const float4*>(
                    (tk < 16) ? (warp_kv + tk * 20) : (pb + AA + hb));
                float4 k0 = kk[0], k1 = kk[1], k2 = kk[2], k3 = kk[3];
                float d = q[0]*k0.x + q[1]*k0.y + q[2]*k0.z + q[3]*k0.w
                        + q[4]*k1.x + q[5]*k1.y + q[6]*k1.z + q[7]*k1.w
                        + q[8]*k2.x + q[9]*k2.y + q[10]*k2.z + q[11]*k2.w
                        + q[12]*k3.x + q[13]*k3.y + q[14]*k3.z + q[15]*k3.w;
                d *= 0.25f;
                scores[l * 18 + tk] = d;
                mxv = fmaxf(mxv, d);
            }

            float den = 0.f;
#pragma unroll
            for (int tk = 0; tk < 17; tk++) {
                float wgt = expf(scores[l * 18 + tk] - mxv);
                if (tk == 16) wgt *= 48.f;
                den += wgt;
                const float4* vv = reinterpret_cast<const float4*>(
                    (tk < 16) ? (warp_kv + 320 + tk * 20) : (pb + 2 * AA + hb));
                float4 v0 = vv[0], v1 = vv[1], v2 = vv[2], v3 = vv[3];
                ctx[0]  += wgt*v0.x; ctx[1]  += wgt*v0.y; ctx[2]  += wgt*v0.z; ctx[3]  += wgt*v0.w;
                ctx[4]  += wgt*v1.x; ctx[5]  += wgt*v1.y; ctx[6]  += wgt*v1.z; ctx[7]  += wgt*v1.w;
                ctx[8]  += wgt*v2.x; ctx[9]  += wgt*v2.y; ctx[10] += wgt*v2.z; ctx[11] += wgt*v2.w;
                ctx[12] += wgt*v3.x; ctx[13] += wgt*v3.y; ctx[14] += wgt*v3.z; ctx[15] += wgt*v3.w;
            }
            const float qw = ((l < 16) ? 1.f : 48.f) / den;
#pragma unroll
            for (int c = 0; c < 16; c++) ctx[c] *= qw;
        }

#pragma unroll
        for (int c = 0; c < 16; c++) {
            float v = ctx[c];
#pragma unroll
            for (int off = 16; off; off >>= 1) v += __shfl_xor_sync(0xffffffffu, v, off);
            ctx[c] = v;
        }
        if (l == 0) {
            float* dst = g_mctx + (size_t)(batch0 + bl) * AA + hb;
            const float sc = 1.f / 64.f;
#pragma unroll
            for (int c = 0; c < 16; c++) dst[c] = ctx[c] * sc;
        }
        __syncwarp();
    }
}

// ---------------- launch ----------------
extern "C" void kernel_launch(void* const* d_in, const int* in_sizes, int n_in,
                              void* d_out, int out_size)
{
    const float* x     = (const float*)d_in[0];
    const float* af    = (const float*)d_in[1];
    const float* costs = (const float*)d_in[2];
    const float* ue_w1 = (const float*)d_in[3];
    const float* ue_b1 = (const float*)d_in[4];
    const float* ue_w2 = (const float*)d_in[5];
    const float* ue_b2 = (const float*)d_in[6];
    const float* fi_w1 = (const float*)d_in[7];
    const float* fi_b1 = (const float*)d_in[8];
    const float* fi_w2 = (const float*)d_in[9];
    const float* fi_b2 = (const float*)d_in[10];
    const float* sd_w1 = (const float*)d_in[11];
    const float* sd_b1 = (const float*)d_in[12];
    const float* sd_w2 = (const float*)d_in[13];
    const float* sd_b2 = (const float*)d_in[14];
    const float* enc_w = (const float*)d_in[15];
    const float* enc_b = (const float*)d_in[16];
    const float* ipw   = (const float*)d_in[17];
    const float* ipb   = (const float*)d_in[18];
    const float* outpw = (const float*)d_in[19];
    const float* outpb = (const float*)d_in[20];
    const float* opw   = (const float*)d_in[21];
    const float* opb   = (const float*)d_in[22];

    float* out    = (float*)d_out;
    float* o_enh  = out;
    float* o_unc  = o_enh + (size_t)BB * IND;
    float* o_fi   = o_unc + BB;
    float* o_sp   = o_fi + (size_t)BB * FF;
    float* o_mask = o_sp + (size_t)BB * FF;
    float* o_sc   = o_mask + (size_t)BB * FF;

    cudaFuncSetAttribute(k_fused, cudaFuncAttributeMaxDynamicSharedMemorySize,
                         FUSED_SMEM_BYTES);
    cudaFuncSetAttribute(k_enc, cudaFuncAttributeMaxDynamicSharedMemorySize,
                         ENC_SMEM_BYTES);

    k_stage1<<<dim3(3, 446), 256>>>(x, ue_w1, fi_w1, sd_w1,
                                    ue_b1, fi_b1, sd_b1, fi_w2, sd_w2,
                                    ipw, enc_w);                                // 1
    k_sel<<<BB / 8, 256>>>(ue_w2, ue_b2, fi_b2, sd_b2, costs,
                           o_unc, o_fi, o_sp, o_mask, o_sc);                    // 2
    k_enc<<<dim3(BB / 128, FF + 1), 256, ENC_SMEM_BYTES>>>(af, enc_b,
                                           opw, outpw, outpb, opb);             // 3
    k_fused<<<BB / 8, 512, FUSED_SMEM_BYTES>>>(ipb);                            // 4 <- profiled
    k_gemm<<<dim3(4, BB / 128), 256>>>(g_mctx, g_Wc, g_bc, x, o_enh,
                                       BB, IND, AA);                            // 5
}